// round 3
// baseline (speedup 1.0000x reference)
#include <cuda_runtime.h>
#include <stdint.h>

#define Nn 100000
#define Ee 1600000
#define EAd 7
#define Hd 64
#define Ld 32
#define Gg 512
#define Cc 6

// ---------------- scratch (static device arrays; no allocs allowed) ----------------
__device__ __align__(256) float g_agg1[Nn];
__device__ __align__(256) float g_h1[Nn * Hd];
__device__ __align__(256) float g_agg2[Nn * Hd];

// ---------------- Threefry-2x32 partitionable (JAX >= 0.4.36 default) ----------------
// bits[j] = out0 ^ out1 of threefry2x32(key=(0,42), counter=(j>>32, j&0xffffffff))
// here j < 2^32 so counter = (0, j).
__device__ __forceinline__ float tf_normal(unsigned j) {
    unsigned x0 = 0u;       // counts_hi
    unsigned x1 = j;        // counts_lo
    const unsigned k0 = 0u, k1 = 42u;
    const unsigned k2 = k0 ^ k1 ^ 0x1BD11BDAu;
    x0 += k0; x1 += k1;
    const int R0[4] = {13, 15, 26, 6};
    const int R1[4] = {17, 29, 16, 24};
#pragma unroll
    for (int i = 0; i < 5; i++) {
#pragma unroll
        for (int r = 0; r < 4; r++) {
            int rr = ((i & 1) == 0) ? R0[r] : R1[r];
            x0 += x1;
            x1 = (x1 << rr) | (x1 >> (32 - rr));
            x1 ^= x0;
        }
        unsigned a0 = (i % 3 == 0) ? k1 : (i % 3 == 1) ? k2 : k0;  // ks[(i+1)%3]
        unsigned a1 = (i % 3 == 0) ? k2 : (i % 3 == 1) ? k0 : k1;  // ks[(i+2)%3]
        x0 += a0;
        x1 += a1 + (unsigned)(i + 1);
    }
    unsigned bits = x0 ^ x1;

    // uniform [lo, 1): f in [0,1) from top 23 bits; u = f*(hi-lo) + lo, non-fused like XLA
    float f = __fadd_rn(__uint_as_float((bits >> 9) | 0x3f800000u), -1.0f);
    const float lo = -0.99999994f;
    float u = __fadd_rn(__fmul_rn(f, 2.0f), lo);
    u = fmaxf(u, lo);

    // XLA ErfInv f32 (Giles) polynomial
    float w = -log1pf(-u * u);
    float p;
    if (w < 5.0f) {
        w -= 2.5f;
        p = 2.81022636e-08f;
        p = fmaf(p, w, 3.43273939e-07f);
        p = fmaf(p, w, -3.5233877e-06f);
        p = fmaf(p, w, -4.39150654e-06f);
        p = fmaf(p, w, 0.00021858087f);
        p = fmaf(p, w, -0.00125372503f);
        p = fmaf(p, w, -0.00417768164f);
        p = fmaf(p, w, 0.246640727f);
        p = fmaf(p, w, 1.50140941f);
    } else {
        w = sqrtf(w) - 3.0f;
        p = -0.000200214257f;
        p = fmaf(p, w, 0.000100950558f);
        p = fmaf(p, w, 0.00134934322f);
        p = fmaf(p, w, -0.00367342844f);
        p = fmaf(p, w, 0.00573950773f);
        p = fmaf(p, w, -0.0076224613f);
        p = fmaf(p, w, 0.00943887047f);
        p = fmaf(p, w, 1.00167406f);
        p = fmaf(p, w, 2.83297682f);
    }
    return 1.41421356f * (p * u);  // sqrt(2) * erfinv(u)
}

// ---------------- kernels ----------------
__global__ void k_zero() {
    int i = blockIdx.x * blockDim.x + threadIdx.x;
    const int tot = (Nn + Nn * Hd) / 4;  // float4 count
    if (i < tot) {
        float4 z = make_float4(0.f, 0.f, 0.f, 0.f);
        if (i < Nn / 4) ((float4*)g_agg1)[i] = z;
        else            ((float4*)g_agg2)[i - Nn / 4] = z;
    }
}

__global__ void k_conv1_edge(const float* __restrict__ x, const int* __restrict__ ei,
                             const float* __restrict__ ea, const float* __restrict__ We1,
                             const float* __restrict__ be1) {
    int e = blockIdx.x * blockDim.x + threadIdx.x;
    if (e >= Ee) return;
    int s = ei[e];
    int d = ei[Ee + e];
    const float* a = ea + (long long)e * EAd;
    float acc = __ldg(be1);
#pragma unroll
    for (int i = 0; i < EAd; i++) acc += __ldg(a + i) * __ldg(We1 + i);
    float m = fmaxf(x[s] + acc, 0.f);
    atomicAdd(&g_agg1[d], m);
}

// conv1 node MLP: h1 = relu( relu(a*W11 + b11) @ W12 + b12 ),  a = (1+eps)*x + agg1
__global__ void k_conv1_mlp(const float* __restrict__ x, const float* __restrict__ W11,
                            const float* __restrict__ b11, const float* __restrict__ W12,
                            const float* __restrict__ b12, const float* __restrict__ eps1) {
    __shared__ float W12s[Hd * Hd];
    __shared__ float tS[8 * Hd];
    int k = threadIdx.x;  // 64 threads
    for (int i = k; i < Hd * Hd; i += Hd) W12s[i] = W12[i];
    int n0 = blockIdx.x * 8;
    float ep = 1.f + *eps1;
    float w11k = __ldg(W11 + k), b11k = __ldg(b11 + k);
#pragma unroll
    for (int i = 0; i < 8; i++) {
        float a = ep * __ldg(x + n0 + i) + g_agg1[n0 + i];
        tS[i * Hd + k] = fmaxf(a * w11k + b11k, 0.f);
    }
    __syncthreads();
    float acc[8];
    float bk = __ldg(b12 + k);
#pragma unroll
    for (int i = 0; i < 8; i++) acc[i] = bk;
#pragma unroll 4
    for (int j = 0; j < Hd; j++) {
        float w = W12s[j * Hd + k];
#pragma unroll
        for (int i = 0; i < 8; i++) acc[i] += tS[i * Hd + j] * w;
    }
#pragma unroll
    for (int i = 0; i < 8; i++)
        g_h1[(long long)(n0 + i) * Hd + k] = fmaxf(acc[i], 0.f);
}

// conv2 edge: m = relu(h1[src] + ea@We2 + be2); agg2[dst] += m   (16 lanes/edge, float4)
__global__ void k_conv2_edge(const int* __restrict__ ei, const float* __restrict__ ea,
                             const float* __restrict__ We2, const float* __restrict__ be2) {
    __shared__ float We2s[EAd * Hd];
    __shared__ float be2s[Hd];
    int t = threadIdx.x;  // 256
    for (int i = t; i < EAd * Hd; i += 256) We2s[i] = We2[i];
    if (t < Hd) be2s[t] = be2[t];
    __syncthreads();
    int gid = blockIdx.x * 256 + t;
    int e = gid >> 4;
    int l = t & 15;
    if (e >= Ee) return;
    int s = ei[e];
    int d = ei[Ee + e];
    float eav[EAd];
    const float* a = ea + (long long)e * EAd;
#pragma unroll
    for (int i = 0; i < EAd; i++) eav[i] = __ldg(a + i);
    int c0 = l * 4;
    float4 p = make_float4(be2s[c0], be2s[c0 + 1], be2s[c0 + 2], be2s[c0 + 3]);
#pragma unroll
    for (int i = 0; i < EAd; i++) {
        p.x += eav[i] * We2s[i * Hd + c0];
        p.y += eav[i] * We2s[i * Hd + c0 + 1];
        p.z += eav[i] * We2s[i * Hd + c0 + 2];
        p.w += eav[i] * We2s[i * Hd + c0 + 3];
    }
    const float4 hv = *((const float4*)(g_h1 + (long long)s * Hd + c0));
    float4 m;
    m.x = fmaxf(hv.x + p.x, 0.f);
    m.y = fmaxf(hv.y + p.y, 0.f);
    m.z = fmaxf(hv.z + p.z, 0.f);
    m.w = fmaxf(hv.w + p.w, 0.f);
    float* dst = g_agg2 + (long long)d * Hd + c0;
    asm volatile("red.global.add.v4.f32 [%0], {%1,%2,%3,%4};"
                 :: "l"(dst), "f"(m.x), "f"(m.y), "f"(m.z), "f"(m.w) : "memory");
}

// conv2 node MLP + heads: h2 = relu(relu(hpre@W21+b21)@W22+b22);
// mu = h2@Wmu+bmu; lv = h2@Wlv+blv; z = mu + noise*exp(0.5*lv)
__global__ void k_conv2_mlp(const float* __restrict__ W21, const float* __restrict__ b21,
                            const float* __restrict__ W22, const float* __restrict__ b22,
                            const float* __restrict__ eps2, const float* __restrict__ Wmu,
                            const float* __restrict__ bmu, const float* __restrict__ Wlv,
                            const float* __restrict__ blv, float* __restrict__ outz,
                            float* __restrict__ outmu, float* __restrict__ outlv) {
    __shared__ float W1s[Hd * Hd];
    __shared__ float W2s[Hd * Hd];
    __shared__ float bufA[8 * Hd];
    __shared__ float bufB[8 * Hd];
    int k = threadIdx.x;  // 64 threads
    for (int i = k; i < Hd * Hd; i += Hd) { W1s[i] = W21[i]; W2s[i] = W22[i]; }
    int n0 = blockIdx.x * 8;
    float ep = 1.f + *eps2;
#pragma unroll
    for (int i = 0; i < 8; i++) {
        long long o = (long long)(n0 + i) * Hd + k;
        bufA[i * Hd + k] = ep * g_h1[o] + g_agg2[o];
    }
    __syncthreads();

    float acc[8];
    float b = __ldg(b21 + k);
#pragma unroll
    for (int i = 0; i < 8; i++) acc[i] = b;
#pragma unroll 4
    for (int j = 0; j < Hd; j++) {
        float w = W1s[j * Hd + k];
#pragma unroll
        for (int i = 0; i < 8; i++) acc[i] += bufA[i * Hd + j] * w;
    }
#pragma unroll
    for (int i = 0; i < 8; i++) bufB[i * Hd + k] = fmaxf(acc[i], 0.f);
    __syncthreads();

    b = __ldg(b22 + k);
#pragma unroll
    for (int i = 0; i < 8; i++) acc[i] = b;
#pragma unroll 4
    for (int j = 0; j < Hd; j++) {
        float w = W2s[j * Hd + k];
#pragma unroll
        for (int i = 0; i < 8; i++) acc[i] += bufB[i * Hd + j] * w;
    }
#pragma unroll
    for (int i = 0; i < 8; i++) bufA[i * Hd + k] = fmaxf(acc[i], 0.f);  // h2
    __syncthreads();

    // heads: threads 0..31 -> mu, 32..63 -> logvar
    int l = k & 31;
    const float* Wh = (k < 32) ? Wmu : Wlv;
    b = (k < 32) ? __ldg(bmu + l) : __ldg(blv + l);
#pragma unroll
    for (int i = 0; i < 8; i++) acc[i] = b;
#pragma unroll 4
    for (int j = 0; j < Hd; j++) {
        float w = __ldg(Wh + j * Ld + l);
#pragma unroll
        for (int i = 0; i < 8; i++) acc[i] += bufA[i * Hd + j] * w;
    }
    float* oph = (k < 32) ? outmu : outlv;
#pragma unroll
    for (int i = 0; i < 8; i++) {
        bufB[i * Hd + k] = acc[i];
        oph[(long long)(n0 + i) * Ld + l] = acc[i];
    }
    __syncthreads();

    if (k < 32) {
#pragma unroll
        for (int i = 0; i < 8; i++) {
            float mu = bufB[i * Hd + k];
            float lv = bufB[i * Hd + 32 + k];
            unsigned j = (unsigned)((n0 + i) * Ld + k);
            float z = mu + tf_normal(j) * expf(0.5f * lv);
            outz[(long long)(n0 + i) * Ld + k] = z;
        }
    }
}

// pooling + classifier: one block per graph; batch is sorted -> binary-search bounds
__global__ void k_pool(const float* __restrict__ z, const int* __restrict__ batch,
                       const float* __restrict__ Wc, const float* __restrict__ bc,
                       float* __restrict__ logits) {
    int g = blockIdx.x;
    int k = threadIdx.x;  // 32
    __shared__ float emb[Ld];
    __shared__ int bounds[2];
    if (k < 2) {
        int target = g + k;
        int lo = 0, hi = Nn;
        while (lo < hi) {
            int mid = (lo + hi) >> 1;
            if (batch[mid] < target) lo = mid + 1; else hi = mid;
        }
        bounds[k] = lo;
    }
    __syncthreads();
    int s = bounds[0], e = bounds[1];
    float acc = 0.f;
    for (int n = s; n < e; n++) acc += z[(long long)n * Ld + k];
    float cnt = (float)(e - s);
    emb[k] = acc / fmaxf(cnt, 1.f);
    __syncthreads();
    if (k < Cc) {
        float o = __ldg(bc + k);
#pragma unroll
        for (int l = 0; l < Ld; l++) o += emb[l] * __ldg(Wc + l * Cc + k);
        logits[g * Cc + k] = o;
    }
}

// ---------------- launcher ----------------
extern "C" void kernel_launch(void* const* d_in, const int* in_sizes, int n_in,
                              void* d_out, int out_size) {
    const float* x     = (const float*)d_in[0];
    const int*   ei    = (const int*)d_in[1];
    const float* ea    = (const float*)d_in[2];
    const int*   batch = (const int*)d_in[3];
    const float* We1 = (const float*)d_in[4];
    const float* be1 = (const float*)d_in[5];
    const float* W11 = (const float*)d_in[6];
    const float* b11 = (const float*)d_in[7];
    const float* W12 = (const float*)d_in[8];
    const float* b12 = (const float*)d_in[9];
    const float* eps1 = (const float*)d_in[10];
    const float* We2 = (const float*)d_in[11];
    const float* be2 = (const float*)d_in[12];
    const float* W21 = (const float*)d_in[13];
    const float* b21 = (const float*)d_in[14];
    const float* W22 = (const float*)d_in[15];
    const float* b22 = (const float*)d_in[16];
    const float* eps2 = (const float*)d_in[17];
    const float* Wmu = (const float*)d_in[18];
    const float* bmu = (const float*)d_in[19];
    const float* Wlv = (const float*)d_in[20];
    const float* blv = (const float*)d_in[21];
    const float* Wc  = (const float*)d_in[22];
    const float* bc  = (const float*)d_in[23];

    float* out = (float*)d_out;
    float* dz  = out;                       // [N, L]
    float* dmu = out + (size_t)Nn * Ld;     // [N, L]
    float* dlv = out + (size_t)2 * Nn * Ld; // [N, L]
    float* dlg = out + (size_t)3 * Nn * Ld; // [G, C]

    const int ztot = (Nn + Nn * Hd) / 4;
    k_zero<<<(ztot + 255) / 256, 256>>>();
    k_conv1_edge<<<(Ee + 255) / 256, 256>>>(x, ei, ea, We1, be1);
    k_conv1_mlp<<<Nn / 8, Hd>>>(x, W11, b11, W12, b12, eps1);
    k_conv2_edge<<<(Ee * 16) / 256, 256>>>(ei, ea, We2, be2);
    k_conv2_mlp<<<Nn / 8, Hd>>>(W21, b21, W22, b22, eps2, Wmu, bmu, Wlv, blv, dz, dmu, dlv);
    k_pool<<<Gg, Ld>>>(dz, batch, Wc, bc, dlg);
}

// round 5
// speedup vs baseline: 1.2471x; 1.2471x over previous
#include <cuda_runtime.h>
#include <stdint.h>

#define Nn 100000
#define Ee 1600000
#define EAd 7
#define Hd 64
#define Ld 32
#define Gg 512
#define Cc 6

// ---------------- scratch ----------------
__device__ __align__(256) float g_agg1[Nn];
__device__ __align__(256) float g_h1[Nn * Hd];
__device__ __align__(256) float g_agg2[Nn * Hd];

// ---------------- Threefry-2x32 partitionable (JAX >= 0.4.36 default) ----------------
__device__ __forceinline__ float tf_normal(unsigned j) {
    unsigned x0 = 0u;       // counts_hi
    unsigned x1 = j;        // counts_lo
    const unsigned k0 = 0u, k1 = 42u;
    const unsigned k2 = k0 ^ k1 ^ 0x1BD11BDAu;
    x0 += k0; x1 += k1;
    const int R0[4] = {13, 15, 26, 6};
    const int R1[4] = {17, 29, 16, 24};
#pragma unroll
    for (int i = 0; i < 5; i++) {
#pragma unroll
        for (int r = 0; r < 4; r++) {
            int rr = ((i & 1) == 0) ? R0[r] : R1[r];
            x0 += x1;
            x1 = (x1 << rr) | (x1 >> (32 - rr));
            x1 ^= x0;
        }
        unsigned a0 = (i % 3 == 0) ? k1 : (i % 3 == 1) ? k2 : k0;
        unsigned a1 = (i % 3 == 0) ? k2 : (i % 3 == 1) ? k0 : k1;
        x0 += a0;
        x1 += a1 + (unsigned)(i + 1);
    }
    unsigned bits = x0 ^ x1;

    float f = __fadd_rn(__uint_as_float((bits >> 9) | 0x3f800000u), -1.0f);
    const float lo = -0.99999994f;
    float u = __fadd_rn(__fmul_rn(f, 2.0f), lo);
    u = fmaxf(u, lo);

    float w = -log1pf(-u * u);
    float p;
    if (w < 5.0f) {
        w -= 2.5f;
        p = 2.81022636e-08f;
        p = fmaf(p, w, 3.43273939e-07f);
        p = fmaf(p, w, -3.5233877e-06f);
        p = fmaf(p, w, -4.39150654e-06f);
        p = fmaf(p, w, 0.00021858087f);
        p = fmaf(p, w, -0.00125372503f);
        p = fmaf(p, w, -0.00417768164f);
        p = fmaf(p, w, 0.246640727f);
        p = fmaf(p, w, 1.50140941f);
    } else {
        w = sqrtf(w) - 3.0f;
        p = -0.000200214257f;
        p = fmaf(p, w, 0.000100950558f);
        p = fmaf(p, w, 0.00134934322f);
        p = fmaf(p, w, -0.00367342844f);
        p = fmaf(p, w, 0.00573950773f);
        p = fmaf(p, w, -0.0076224613f);
        p = fmaf(p, w, 0.00943887047f);
        p = fmaf(p, w, 1.00167406f);
        p = fmaf(p, w, 2.83297682f);
    }
    return 1.41421356f * (p * u);
}

// ---------------- kernels ----------------
__global__ void k_zero() {
    int i = blockIdx.x * blockDim.x + threadIdx.x;
    const int tot = (Nn + Nn * Hd) / 4;
    if (i < tot) {
        float4 z = make_float4(0.f, 0.f, 0.f, 0.f);
        if (i < Nn / 4) ((float4*)g_agg1)[i] = z;
        else            ((float4*)g_agg2)[i - Nn / 4] = z;
    }
}

__global__ void k_conv1_edge(const float* __restrict__ x, const int* __restrict__ ei,
                             const float* __restrict__ ea, const float* __restrict__ We1,
                             const float* __restrict__ be1) {
    int e = blockIdx.x * blockDim.x + threadIdx.x;
    if (e >= Ee) return;
    int s = ei[e];
    int d = ei[Ee + e];
    const float* a = ea + (long long)e * EAd;
    float acc = __ldg(be1);
#pragma unroll
    for (int i = 0; i < EAd; i++) acc += __ldg(a + i) * __ldg(We1 + i);
    float m = fmaxf(x[s] + acc, 0.f);
    atomicAdd(&g_agg1[d], m);
}

// conv1 node MLP: h1 = relu( relu(a*W11 + b11) @ W12 + b12 ),  a = (1+eps)*x + agg1
// thread k owns output column k; W12 column in registers; tS read as broadcast LDS.128
__global__ void k_conv1_mlp(const float* __restrict__ x, const float* __restrict__ W11,
                            const float* __restrict__ b11, const float* __restrict__ W12,
                            const float* __restrict__ b12, const float* __restrict__ eps1) {
    __shared__ float tS[8 * Hd];
    int k = threadIdx.x;  // 64
    float wcol[Hd];
#pragma unroll
    for (int j = 0; j < Hd; j++) wcol[j] = __ldg(W12 + j * Hd + k);

    int n0 = blockIdx.x * 8;
    float ep = 1.f + *eps1;
    float w11k = __ldg(W11 + k), b11k = __ldg(b11 + k);
#pragma unroll
    for (int i = 0; i < 8; i++) {
        float a = ep * __ldg(x + n0 + i) + g_agg1[n0 + i];
        tS[i * Hd + k] = fmaxf(a * w11k + b11k, 0.f);
    }
    __syncthreads();
    float acc[8];
    float bk = __ldg(b12 + k);
#pragma unroll
    for (int i = 0; i < 8; i++) acc[i] = bk;
#pragma unroll
    for (int jq = 0; jq < Hd / 4; jq++) {
#pragma unroll
        for (int i = 0; i < 8; i++) {
            float4 v = *(const float4*)&tS[i * Hd + jq * 4];
            acc[i] = fmaf(v.x, wcol[jq * 4 + 0], acc[i]);
            acc[i] = fmaf(v.y, wcol[jq * 4 + 1], acc[i]);
            acc[i] = fmaf(v.z, wcol[jq * 4 + 2], acc[i]);
            acc[i] = fmaf(v.w, wcol[jq * 4 + 3], acc[i]);
        }
    }
#pragma unroll
    for (int i = 0; i < 8; i++)
        g_h1[(long long)(n0 + i) * Hd + k] = fmaxf(acc[i], 0.f);
}

// conv2 edge: 8 lanes/edge, weights in registers, grid-stride
__global__ void __launch_bounds__(256) k_conv2_edge(
        const int* __restrict__ ei, const float* __restrict__ ea,
        const float* __restrict__ We2, const float* __restrict__ be2) {
    int t = threadIdx.x;  // 256
    int lane = t & 7;
    int c0 = lane * 8;
    float4 wr0[EAd], wr1[EAd];
#pragma unroll
    for (int i = 0; i < EAd; i++) {
        wr0[i] = *(const float4*)&We2[i * Hd + c0];
        wr1[i] = *(const float4*)&We2[i * Hd + c0 + 4];
    }
    float4 br0 = *(const float4*)&be2[c0];
    float4 br1 = *(const float4*)&be2[c0 + 4];

    int group = (blockIdx.x * 256 + t) >> 3;
    int nGroups = (gridDim.x * 256) >> 3;
    for (int e = group; e < Ee; e += nGroups) {
        int s = __ldg(ei + e);
        int d = __ldg(ei + Ee + e);
        float4 p0 = br0, p1 = br1;
        const float* a = ea + (long long)e * EAd;
#pragma unroll
        for (int i = 0; i < EAd; i++) {
            float av = __ldg(a + i);
            p0.x = fmaf(av, wr0[i].x, p0.x);
            p0.y = fmaf(av, wr0[i].y, p0.y);
            p0.z = fmaf(av, wr0[i].z, p0.z);
            p0.w = fmaf(av, wr0[i].w, p0.w);
            p1.x = fmaf(av, wr1[i].x, p1.x);
            p1.y = fmaf(av, wr1[i].y, p1.y);
            p1.z = fmaf(av, wr1[i].z, p1.z);
            p1.w = fmaf(av, wr1[i].w, p1.w);
        }
        const float4* hp = (const float4*)(g_h1 + (long long)s * Hd + c0);
        float4 h0 = hp[0], h1v = hp[1];
        float4 m0, m1;
        m0.x = fmaxf(h0.x + p0.x, 0.f);
        m0.y = fmaxf(h0.y + p0.y, 0.f);
        m0.z = fmaxf(h0.z + p0.z, 0.f);
        m0.w = fmaxf(h0.w + p0.w, 0.f);
        m1.x = fmaxf(h1v.x + p1.x, 0.f);
        m1.y = fmaxf(h1v.y + p1.y, 0.f);
        m1.z = fmaxf(h1v.z + p1.z, 0.f);
        m1.w = fmaxf(h1v.w + p1.w, 0.f);
        float* dst = g_agg2 + (long long)d * Hd + c0;
        asm volatile("red.global.add.v4.f32 [%0], {%1,%2,%3,%4};"
                     :: "l"(dst), "f"(m0.x), "f"(m0.y), "f"(m0.z), "f"(m0.w) : "memory");
        asm volatile("red.global.add.v4.f32 [%0], {%1,%2,%3,%4};"
                     :: "l"(dst + 4), "f"(m1.x), "f"(m1.y), "f"(m1.z), "f"(m1.w) : "memory");
    }
}

// conv2 node MLP + heads (weight columns in registers, broadcast LDS.128 activations)
__global__ void k_conv2_mlp(const float* __restrict__ W21, const float* __restrict__ b21,
                            const float* __restrict__ W22, const float* __restrict__ b22,
                            const float* __restrict__ eps2, const float* __restrict__ Wmu,
                            const float* __restrict__ bmu, const float* __restrict__ Wlv,
                            const float* __restrict__ blv, float* __restrict__ outz,
                            float* __restrict__ outmu, float* __restrict__ outlv) {
    __shared__ float bufA[8 * Hd];
    __shared__ float bufB[8 * Hd];
    int k = threadIdx.x;  // 64
    int n0 = blockIdx.x * 8;
    float ep = 1.f + *eps2;

    float wcol[Hd];
#pragma unroll
    for (int j = 0; j < Hd; j++) wcol[j] = __ldg(W21 + j * Hd + k);

#pragma unroll
    for (int i = 0; i < 8; i++) {
        long long o = (long long)(n0 + i) * Hd + k;
        bufA[i * Hd + k] = ep * g_h1[o] + g_agg2[o];
    }
    __syncthreads();

    float acc[8];
    float b = __ldg(b21 + k);
#pragma unroll
    for (int i = 0; i < 8; i++) acc[i] = b;
#pragma unroll
    for (int jq = 0; jq < Hd / 4; jq++) {
#pragma unroll
        for (int i = 0; i < 8; i++) {
            float4 v = *(const float4*)&bufA[i * Hd + jq * 4];
            acc[i] = fmaf(v.x, wcol[jq * 4 + 0], acc[i]);
            acc[i] = fmaf(v.y, wcol[jq * 4 + 1], acc[i]);
            acc[i] = fmaf(v.z, wcol[jq * 4 + 2], acc[i]);
            acc[i] = fmaf(v.w, wcol[jq * 4 + 3], acc[i]);
        }
    }
#pragma unroll
    for (int i = 0; i < 8; i++) bufB[i * Hd + k] = fmaxf(acc[i], 0.f);

#pragma unroll
    for (int j = 0; j < Hd; j++) wcol[j] = __ldg(W22 + j * Hd + k);
    __syncthreads();

    b = __ldg(b22 + k);
#pragma unroll
    for (int i = 0; i < 8; i++) acc[i] = b;
#pragma unroll
    for (int jq = 0; jq < Hd / 4; jq++) {
#pragma unroll
        for (int i = 0; i < 8; i++) {
            float4 v = *(const float4*)&bufB[i * Hd + jq * 4];
            acc[i] = fmaf(v.x, wcol[jq * 4 + 0], acc[i]);
            acc[i] = fmaf(v.y, wcol[jq * 4 + 1], acc[i]);
            acc[i] = fmaf(v.z, wcol[jq * 4 + 2], acc[i]);
            acc[i] = fmaf(v.w, wcol[jq * 4 + 3], acc[i]);
        }
    }
    __syncthreads();
#pragma unroll
    for (int i = 0; i < 8; i++) bufA[i * Hd + k] = fmaxf(acc[i], 0.f);  // h2

    // heads: threads 0..31 -> mu col l, 32..63 -> logvar col l
    int l = k & 31;
    const float* Wh = (k < 32) ? Wmu : Wlv;
#pragma unroll
    for (int j = 0; j < Hd; j++) wcol[j] = __ldg(Wh + j * Ld + l);
    __syncthreads();

    b = (k < 32) ? __ldg(bmu + l) : __ldg(blv + l);
#pragma unroll
    for (int i = 0; i < 8; i++) acc[i] = b;
#pragma unroll
    for (int jq = 0; jq < Hd / 4; jq++) {
#pragma unroll
        for (int i = 0; i < 8; i++) {
            float4 v = *(const float4*)&bufA[i * Hd + jq * 4];
            acc[i] = fmaf(v.x, wcol[jq * 4 + 0], acc[i]);
            acc[i] = fmaf(v.y, wcol[jq * 4 + 1], acc[i]);
            acc[i] = fmaf(v.z, wcol[jq * 4 + 2], acc[i]);
            acc[i] = fmaf(v.w, wcol[jq * 4 + 3], acc[i]);
        }
    }
    float* oph = (k < 32) ? outmu : outlv;
#pragma unroll
    for (int i = 0; i < 8; i++) {
        bufB[i * Hd + k] = acc[i];
        oph[(long long)(n0 + i) * Ld + l] = acc[i];
    }
    __syncthreads();

    if (k < 32) {
#pragma unroll
        for (int i = 0; i < 8; i++) {
            float mu = bufB[i * Hd + k];
            float lv = bufB[i * Hd + 32 + k];
            unsigned j = (unsigned)((n0 + i) * Ld + k);
            float z = mu + tf_normal(j) * expf(0.5f * lv);
            outz[(long long)(n0 + i) * Ld + k] = z;
        }
    }
}

// pooling + classifier
__global__ void k_pool(const float* __restrict__ z, const int* __restrict__ batch,
                       const float* __restrict__ Wc, const float* __restrict__ bc,
                       float* __restrict__ logits) {
    int g = blockIdx.x;
    int k = threadIdx.x;  // 32
    __shared__ float emb[Ld];
    __shared__ int bounds[2];
    if (k < 2) {
        int target = g + k;
        int lo = 0, hi = Nn;
        while (lo < hi) {
            int mid = (lo + hi) >> 1;
            if (batch[mid] < target) lo = mid + 1; else hi = mid;
        }
        bounds[k] = lo;
    }
    __syncthreads();
    int s = bounds[0], e = bounds[1];
    float acc = 0.f;
    for (int n = s; n < e; n++) acc += z[(long long)n * Ld + k];
    float cnt = (float)(e - s);
    emb[k] = acc / fmaxf(cnt, 1.f);
    __syncthreads();
    if (k < Cc) {
        float o = __ldg(bc + k);
#pragma unroll
        for (int l = 0; l < Ld; l++) o += emb[l] * __ldg(Wc + l * Cc + k);
        logits[g * Cc + k] = o;
    }
}

// ---------------- launcher ----------------
extern "C" void kernel_launch(void* const* d_in, const int* in_sizes, int n_in,
                              void* d_out, int out_size) {
    const float* x     = (const float*)d_in[0];
    const int*   ei    = (const int*)d_in[1];
    const float* ea    = (const float*)d_in[2];
    const int*   batch = (const int*)d_in[3];
    const float* We1 = (const float*)d_in[4];
    const float* be1 = (const float*)d_in[5];
    const float* W11 = (const float*)d_in[6];
    const float* b11 = (const float*)d_in[7];
    const float* W12 = (const float*)d_in[8];
    const float* b12 = (const float*)d_in[9];
    const float* eps1 = (const float*)d_in[10];
    const float* We2 = (const float*)d_in[11];
    const float* be2 = (const float*)d_in[12];
    const float* W21 = (const float*)d_in[13];
    const float* b21 = (const float*)d_in[14];
    const float* W22 = (const float*)d_in[15];
    const float* b22 = (const float*)d_in[16];
    const float* eps2 = (const float*)d_in[17];
    const float* Wmu = (const float*)d_in[18];
    const float* bmu = (const float*)d_in[19];
    const float* Wlv = (const float*)d_in[20];
    const float* blv = (const float*)d_in[21];
    const float* Wc  = (const float*)d_in[22];
    const float* bc  = (const float*)d_in[23];

    float* out = (float*)d_out;
    float* dz  = out;
    float* dmu = out + (size_t)Nn * Ld;
    float* dlv = out + (size_t)2 * Nn * Ld;
    float* dlg = out + (size_t)3 * Nn * Ld;

    const int ztot = (Nn + Nn * Hd) / 4;
    k_zero<<<(ztot + 255) / 256, 256>>>();
    k_conv1_edge<<<(Ee + 255) / 256, 256>>>(x, ei, ea, We1, be1);
    k_conv1_mlp<<<Nn / 8, Hd>>>(x, W11, b11, W12, b12, eps1);
    k_conv2_edge<<<1184, 256>>>(ei, ea, We2, be2);
    k_conv2_mlp<<<Nn / 8, Hd>>>(W21, b21, W22, b22, eps2, Wmu, bmu, Wlv, blv, dz, dmu, dlv);
    k_pool<<<Gg, Ld>>>(dz, batch, Wc, bc, dlg);
}

// round 6
// speedup vs baseline: 1.5198x; 1.2186x over previous
#include <cuda_runtime.h>
#include <stdint.h>

#define Nn 100000
#define Ee 1600000
#define EAd 7
#define Hd 64
#define Ld 32
#define Gg 512
#define Cc 6

// ---------------- scratch ----------------
__device__ __align__(256) float g_agg1[Nn];
__device__ __align__(256) float g_h1[Nn * Hd];
__device__ __align__(256) float g_agg2[Nn * Hd];

// ---------------- Threefry-2x32 partitionable (JAX >= 0.4.36 default) ----------------
__device__ __forceinline__ float tf_normal(unsigned j) {
    unsigned x0 = 0u;       // counts_hi
    unsigned x1 = j;        // counts_lo
    const unsigned k0 = 0u, k1 = 42u;
    const unsigned k2 = k0 ^ k1 ^ 0x1BD11BDAu;
    x0 += k0; x1 += k1;
    const int R0[4] = {13, 15, 26, 6};
    const int R1[4] = {17, 29, 16, 24};
#pragma unroll
    for (int i = 0; i < 5; i++) {
#pragma unroll
        for (int r = 0; r < 4; r++) {
            int rr = ((i & 1) == 0) ? R0[r] : R1[r];
            x0 += x1;
            x1 = (x1 << rr) | (x1 >> (32 - rr));
            x1 ^= x0;
        }
        unsigned a0 = (i % 3 == 0) ? k1 : (i % 3 == 1) ? k2 : k0;
        unsigned a1 = (i % 3 == 0) ? k2 : (i % 3 == 1) ? k0 : k1;
        x0 += a0;
        x1 += a1 + (unsigned)(i + 1);
    }
    unsigned bits = x0 ^ x1;

    float f = __fadd_rn(__uint_as_float((bits >> 9) | 0x3f800000u), -1.0f);
    const float lo = -0.99999994f;
    float u = __fadd_rn(__fmul_rn(f, 2.0f), lo);
    u = fmaxf(u, lo);

    float w = -log1pf(-u * u);
    float p;
    if (w < 5.0f) {
        w -= 2.5f;
        p = 2.81022636e-08f;
        p = fmaf(p, w, 3.43273939e-07f);
        p = fmaf(p, w, -3.5233877e-06f);
        p = fmaf(p, w, -4.39150654e-06f);
        p = fmaf(p, w, 0.00021858087f);
        p = fmaf(p, w, -0.00125372503f);
        p = fmaf(p, w, -0.00417768164f);
        p = fmaf(p, w, 0.246640727f);
        p = fmaf(p, w, 1.50140941f);
    } else {
        w = sqrtf(w) - 3.0f;
        p = -0.000200214257f;
        p = fmaf(p, w, 0.000100950558f);
        p = fmaf(p, w, 0.00134934322f);
        p = fmaf(p, w, -0.00367342844f);
        p = fmaf(p, w, 0.00573950773f);
        p = fmaf(p, w, -0.0076224613f);
        p = fmaf(p, w, 0.00943887047f);
        p = fmaf(p, w, 1.00167406f);
        p = fmaf(p, w, 2.83297682f);
    }
    return 1.41421356f * (p * u);
}

// ---------------- kernels ----------------
__global__ void k_zero() {
    int i = blockIdx.x * blockDim.x + threadIdx.x;
    const int tot = (Nn + Nn * Hd) / 4;
    if (i < tot) {
        float4 z = make_float4(0.f, 0.f, 0.f, 0.f);
        if (i < Nn / 4) ((float4*)g_agg1)[i] = z;
        else            ((float4*)g_agg2)[i - Nn / 4] = z;
    }
}

// conv1 edge: 4 edges/thread; ea via 7x LDG.128, ei via 2x int4
__global__ void k_conv1_edge(const float* __restrict__ x, const int* __restrict__ ei,
                             const float* __restrict__ ea, const float* __restrict__ We1,
                             const float* __restrict__ be1) {
    int g4 = blockIdx.x * blockDim.x + threadIdx.x;
    if (g4 >= Ee / 4) return;
    int e0 = g4 * 4;

    float w[EAd];
#pragma unroll
    for (int i = 0; i < EAd; i++) w[i] = __ldg(We1 + i);
    float be = __ldg(be1);

    float A[28];
    const float4* ap = (const float4*)(ea + (long long)e0 * EAd);
#pragma unroll
    for (int i = 0; i < 7; i++) *((float4*)&A[i * 4]) = __ldg(ap + i);

    int4 ss = *(const int4*)(ei + e0);
    int4 dd = *(const int4*)(ei + Ee + e0);
    int sv[4] = {ss.x, ss.y, ss.z, ss.w};
    int dv[4] = {dd.x, dd.y, dd.z, dd.w};

#pragma unroll
    for (int j = 0; j < 4; j++) {
        float acc = be;
#pragma unroll
        for (int i = 0; i < EAd; i++) acc = fmaf(A[j * EAd + i], w[i], acc);
        float m = fmaxf(__ldg(x + sv[j]) + acc, 0.f);
        atomicAdd(&g_agg1[dv[j]], m);
    }
}

// conv1 node MLP
__global__ void k_conv1_mlp(const float* __restrict__ x, const float* __restrict__ W11,
                            const float* __restrict__ b11, const float* __restrict__ W12,
                            const float* __restrict__ b12, const float* __restrict__ eps1) {
    __shared__ float tS[8 * Hd];
    int k = threadIdx.x;  // 64
    float wcol[Hd];
#pragma unroll
    for (int j = 0; j < Hd; j++) wcol[j] = __ldg(W12 + j * Hd + k);

    int n0 = blockIdx.x * 8;
    float ep = 1.f + *eps1;
    float w11k = __ldg(W11 + k), b11k = __ldg(b11 + k);
#pragma unroll
    for (int i = 0; i < 8; i++) {
        float a = ep * __ldg(x + n0 + i) + g_agg1[n0 + i];
        tS[i * Hd + k] = fmaxf(a * w11k + b11k, 0.f);
    }
    __syncthreads();
    float acc[8];
    float bk = __ldg(b12 + k);
#pragma unroll
    for (int i = 0; i < 8; i++) acc[i] = bk;
#pragma unroll
    for (int jq = 0; jq < Hd / 4; jq++) {
#pragma unroll
        for (int i = 0; i < 8; i++) {
            float4 v = *(const float4*)&tS[i * Hd + jq * 4];
            acc[i] = fmaf(v.x, wcol[jq * 4 + 0], acc[i]);
            acc[i] = fmaf(v.y, wcol[jq * 4 + 1], acc[i]);
            acc[i] = fmaf(v.z, wcol[jq * 4 + 2], acc[i]);
            acc[i] = fmaf(v.w, wcol[jq * 4 + 3], acc[i]);
        }
    }
#pragma unroll
    for (int i = 0; i < 8; i++)
        g_h1[(long long)(n0 + i) * Hd + k] = fmaxf(acc[i], 0.f);
}

// conv2 edge v3: 16 lanes/edge, 7x float4 weights in regs, 4 CTAs/SM
__global__ void __launch_bounds__(256, 4) k_conv2_edge(
        const int* __restrict__ ei, const float* __restrict__ ea,
        const float* __restrict__ We2, const float* __restrict__ be2) {
    int t = threadIdx.x;  // 256
    int lane = t & 15;
    int c0 = lane * 4;
    float4 wr[EAd];
#pragma unroll
    for (int i = 0; i < EAd; i++) wr[i] = *(const float4*)&We2[i * Hd + c0];
    float4 br = *(const float4*)&be2[c0];

    int group = (blockIdx.x * 256 + t) >> 4;
    int nGroups = (gridDim.x * 256) >> 4;
    for (int e = group; e < Ee; e += nGroups) {
        int s = __ldg(ei + e);
        int d = __ldg(ei + Ee + e);
        float4 p = br;
        const float* a = ea + (long long)e * EAd;
#pragma unroll
        for (int i = 0; i < EAd; i++) {
            float av = __ldg(a + i);
            p.x = fmaf(av, wr[i].x, p.x);
            p.y = fmaf(av, wr[i].y, p.y);
            p.z = fmaf(av, wr[i].z, p.z);
            p.w = fmaf(av, wr[i].w, p.w);
        }
        float4 h = *(const float4*)(g_h1 + (long long)s * Hd + c0);
        float4 m;
        m.x = fmaxf(h.x + p.x, 0.f);
        m.y = fmaxf(h.y + p.y, 0.f);
        m.z = fmaxf(h.z + p.z, 0.f);
        m.w = fmaxf(h.w + p.w, 0.f);
        float* dst = g_agg2 + (long long)d * Hd + c0;
        asm volatile("red.global.add.v4.f32 [%0], {%1,%2,%3,%4};"
                     :: "l"(dst), "f"(m.x), "f"(m.y), "f"(m.z), "f"(m.w) : "memory");
    }
}

// conv2 node MLP + heads
__global__ void k_conv2_mlp(const float* __restrict__ W21, const float* __restrict__ b21,
                            const float* __restrict__ W22, const float* __restrict__ b22,
                            const float* __restrict__ eps2, const float* __restrict__ Wmu,
                            const float* __restrict__ bmu, const float* __restrict__ Wlv,
                            const float* __restrict__ blv, float* __restrict__ outz,
                            float* __restrict__ outmu, float* __restrict__ outlv) {
    __shared__ float bufA[8 * Hd];
    __shared__ float bufB[8 * Hd];
    int k = threadIdx.x;  // 64
    int n0 = blockIdx.x * 8;
    float ep = 1.f + *eps2;

    float wcol[Hd];
#pragma unroll
    for (int j = 0; j < Hd; j++) wcol[j] = __ldg(W21 + j * Hd + k);

#pragma unroll
    for (int i = 0; i < 8; i++) {
        long long o = (long long)(n0 + i) * Hd + k;
        bufA[i * Hd + k] = ep * g_h1[o] + g_agg2[o];
    }
    __syncthreads();

    float acc[8];
    float b = __ldg(b21 + k);
#pragma unroll
    for (int i = 0; i < 8; i++) acc[i] = b;
#pragma unroll
    for (int jq = 0; jq < Hd / 4; jq++) {
#pragma unroll
        for (int i = 0; i < 8; i++) {
            float4 v = *(const float4*)&bufA[i * Hd + jq * 4];
            acc[i] = fmaf(v.x, wcol[jq * 4 + 0], acc[i]);
            acc[i] = fmaf(v.y, wcol[jq * 4 + 1], acc[i]);
            acc[i] = fmaf(v.z, wcol[jq * 4 + 2], acc[i]);
            acc[i] = fmaf(v.w, wcol[jq * 4 + 3], acc[i]);
        }
    }
#pragma unroll
    for (int i = 0; i < 8; i++) bufB[i * Hd + k] = fmaxf(acc[i], 0.f);

#pragma unroll
    for (int j = 0; j < Hd; j++) wcol[j] = __ldg(W22 + j * Hd + k);
    __syncthreads();

    b = __ldg(b22 + k);
#pragma unroll
    for (int i = 0; i < 8; i++) acc[i] = b;
#pragma unroll
    for (int jq = 0; jq < Hd / 4; jq++) {
#pragma unroll
        for (int i = 0; i < 8; i++) {
            float4 v = *(const float4*)&bufB[i * Hd + jq * 4];
            acc[i] = fmaf(v.x, wcol[jq * 4 + 0], acc[i]);
            acc[i] = fmaf(v.y, wcol[jq * 4 + 1], acc[i]);
            acc[i] = fmaf(v.z, wcol[jq * 4 + 2], acc[i]);
            acc[i] = fmaf(v.w, wcol[jq * 4 + 3], acc[i]);
        }
    }
    __syncthreads();
#pragma unroll
    for (int i = 0; i < 8; i++) bufA[i * Hd + k] = fmaxf(acc[i], 0.f);  // h2

    int l = k & 31;
    const float* Wh = (k < 32) ? Wmu : Wlv;
#pragma unroll
    for (int j = 0; j < Hd; j++) wcol[j] = __ldg(Wh + j * Ld + l);
    __syncthreads();

    b = (k < 32) ? __ldg(bmu + l) : __ldg(blv + l);
#pragma unroll
    for (int i = 0; i < 8; i++) acc[i] = b;
#pragma unroll
    for (int jq = 0; jq < Hd / 4; jq++) {
#pragma unroll
        for (int i = 0; i < 8; i++) {
            float4 v = *(const float4*)&bufA[i * Hd + jq * 4];
            acc[i] = fmaf(v.x, wcol[jq * 4 + 0], acc[i]);
            acc[i] = fmaf(v.y, wcol[jq * 4 + 1], acc[i]);
            acc[i] = fmaf(v.z, wcol[jq * 4 + 2], acc[i]);
            acc[i] = fmaf(v.w, wcol[jq * 4 + 3], acc[i]);
        }
    }
    float* oph = (k < 32) ? outmu : outlv;
#pragma unroll
    for (int i = 0; i < 8; i++) {
        bufB[i * Hd + k] = acc[i];
        oph[(long long)(n0 + i) * Ld + l] = acc[i];
    }
    __syncthreads();

    if (k < 32) {
#pragma unroll
        for (int i = 0; i < 8; i++) {
            float mu = bufB[i * Hd + k];
            float lv = bufB[i * Hd + 32 + k];
            unsigned j = (unsigned)((n0 + i) * Ld + k);
            float z = mu + tf_normal(j) * expf(0.5f * lv);
            outz[(long long)(n0 + i) * Ld + k] = z;
        }
    }
}

// pooling + classifier
__global__ void k_pool(const float* __restrict__ z, const int* __restrict__ batch,
                       const float* __restrict__ Wc, const float* __restrict__ bc,
                       float* __restrict__ logits) {
    int g = blockIdx.x;
    int k = threadIdx.x;  // 32
    __shared__ float emb[Ld];
    __shared__ int bounds[2];
    if (k < 2) {
        int target = g + k;
        int lo = 0, hi = Nn;
        while (lo < hi) {
            int mid = (lo + hi) >> 1;
            if (batch[mid] < target) lo = mid + 1; else hi = mid;
        }
        bounds[k] = lo;
    }
    __syncthreads();
    int s = bounds[0], e = bounds[1];
    float acc = 0.f;
    for (int n = s; n < e; n++) acc += z[(long long)n * Ld + k];
    float cnt = (float)(e - s);
    emb[k] = acc / fmaxf(cnt, 1.f);
    __syncthreads();
    if (k < Cc) {
        float o = __ldg(bc + k);
#pragma unroll
        for (int l = 0; l < Ld; l++) o += emb[l] * __ldg(Wc + l * Cc + k);
        logits[g * Cc + k] = o;
    }
}

// ---------------- launcher ----------------
extern "C" void kernel_launch(void* const* d_in, const int* in_sizes, int n_in,
                              void* d_out, int out_size) {
    const float* x     = (const float*)d_in[0];
    const int*   ei    = (const int*)d_in[1];
    const float* ea    = (const float*)d_in[2];
    const int*   batch = (const int*)d_in[3];
    const float* We1 = (const float*)d_in[4];
    const float* be1 = (const float*)d_in[5];
    const float* W11 = (const float*)d_in[6];
    const float* b11 = (const float*)d_in[7];
    const float* W12 = (const float*)d_in[8];
    const float* b12 = (const float*)d_in[9];
    const float* eps1 = (const float*)d_in[10];
    const float* We2 = (const float*)d_in[11];
    const float* be2 = (const float*)d_in[12];
    const float* W21 = (const float*)d_in[13];
    const float* b21 = (const float*)d_in[14];
    const float* W22 = (const float*)d_in[15];
    const float* b22 = (const float*)d_in[16];
    const float* eps2 = (const float*)d_in[17];
    const float* Wmu = (const float*)d_in[18];
    const float* bmu = (const float*)d_in[19];
    const float* Wlv = (const float*)d_in[20];
    const float* blv = (const float*)d_in[21];
    const float* Wc  = (const float*)d_in[22];
    const float* bc  = (const float*)d_in[23];

    float* out = (float*)d_out;
    float* dz  = out;
    float* dmu = out + (size_t)Nn * Ld;
    float* dlv = out + (size_t)2 * Nn * Ld;
    float* dlg = out + (size_t)3 * Nn * Ld;

    const int ztot = (Nn + Nn * Hd) / 4;
    k_zero<<<(ztot + 255) / 256, 256>>>();
    k_conv1_edge<<<(Ee / 4 + 255) / 256, 256>>>(x, ei, ea, We1, be1);
    k_conv1_mlp<<<Nn / 8, Hd>>>(x, W11, b11, W12, b12, eps1);
    k_conv2_edge<<<592, 256>>>(ei, ea, We2, be2);
    k_conv2_mlp<<<Nn / 8, Hd>>>(W21, b21, W22, b22, eps2, Wmu, bmu, Wlv, blv, dz, dmu, dlv);
    k_pool<<<Gg, Ld>>>(dz, batch, Wc, bc, dlg);
}